// round 2
// baseline (speedup 1.0000x reference)
#include <cuda_runtime.h>
#include <cuda_bf16.h>
#include <stdint.h>

// Problem constants (from reference)
#define N_NODES  50000
#define N_EDGES  800000
#define IN_F     128
#define OUT_F    128

// Scratch: device globals (no allocation allowed).
// 16B alignment required for red.global.add.v4.f32.
__device__ __align__(16) float g_agg[N_NODES * IN_F];   // 25.6 MB
__device__ float g_deg[N_NODES];

// ---------------------------------------------------------------------------
// Kernel 1: zero scratch
// ---------------------------------------------------------------------------
__global__ void zero_kernel() {
    const int tid    = blockIdx.x * blockDim.x + threadIdx.x;
    const int stride = gridDim.x * blockDim.x;
    float4* agg4 = reinterpret_cast<float4*>(g_agg);
    const int n4 = (N_NODES * IN_F) / 4;   // 1.6M
    for (int i = tid; i < n4; i += stride)
        agg4[i] = make_float4(0.f, 0.f, 0.f, 0.f);
    for (int i = tid; i < N_NODES; i += stride)
        g_deg[i] = 0.f;
}

// ---------------------------------------------------------------------------
// Kernel 2: edge scatter. One warp per edge: 32 lanes x float4 = 128 floats.
// edge_index arrives as int32 (harness downcasts int64 -> int32 per contract).
// x gather hits L2 (x fits); accumulation via red.global.add.v4.f32 (no-return
// vector reduction, sm_90+), 1 op per lane per edge.
// ---------------------------------------------------------------------------
__global__ void __launch_bounds__(256, 8)
scatter_kernel(const float4* __restrict__ x4, const int* __restrict__ ei) {
    const int warp = (blockIdx.x * blockDim.x + threadIdx.x) >> 5;
    if (warp >= N_EDGES) return;
    const int lane = threadIdx.x & 31;

    // Defensive clamp: guarantees no OOB even if dtype assumption is wrong.
    int src = ei[warp];            // row 0: sources
    int dst = ei[N_EDGES + warp];  // row 1: destinations
    src = min(max(src, 0), N_NODES - 1);
    dst = min(max(dst, 0), N_NODES - 1);

    float4 v = __ldg(&x4[src * (IN_F / 4) + lane]);

    float* p = g_agg + (size_t)dst * IN_F + lane * 4;
    asm volatile("red.global.add.v4.f32 [%0], {%1, %2, %3, %4};"
                 :: "l"(p), "f"(v.x), "f"(v.y), "f"(v.z), "f"(v.w)
                 : "memory");

    if (lane == 0)
        atomicAdd(&g_deg[dst], 1.0f);
}

// ---------------------------------------------------------------------------
// Kernel 3: out[m][n] = (agg[m][:]/max(deg[m],1)) . W[n][:] + b[n]
// Block tile: 64 rows x 128 cols, 256 threads, 4x8 per-thread microtile.
// Smem: Wsm transposed [k][n] 64KB + Hsm [64][128] 32KB + invdeg[64]
// -> 96.5KB dynamic smem (1 block/SM).
// ---------------------------------------------------------------------------
#define TILE_M 64
__global__ void __launch_bounds__(256, 1)
gemm_kernel(float* __restrict__ out, const float* __restrict__ W,
            const float* __restrict__ b) {
    extern __shared__ float sm[];
    float* Wsm    = sm;                       // [128][128], layout [k][n]
    float* Hsm    = sm + IN_F * OUT_F;        // [TILE_M][128]
    float* invdeg = Hsm + TILE_M * IN_F;      // [TILE_M]

    const int tid = threadIdx.x;
    const int m0  = blockIdx.x * TILE_M;

    // Stage W transposed: Wsm[k*128 + n] = W[n*128 + k]
    #pragma unroll 4
    for (int i = tid; i < OUT_F * IN_F; i += 256) {
        const int n = i >> 7;
        const int k = i & 127;
        Wsm[k * OUT_F + n] = W[i];
    }

    // Per-row inverse degree
    if (tid < TILE_M) {
        const int m = m0 + tid;
        invdeg[tid] = (m < N_NODES) ? (1.0f / fmaxf(g_deg[m], 1.0f)) : 0.0f;
    }
    __syncthreads();

    // Stage H tile = agg * invdeg   (TILE_M*128 = 8192 floats = 2048 float4)
    const float4* agg4 = reinterpret_cast<const float4*>(g_agg);
    #pragma unroll 2
    for (int i = tid; i < TILE_M * (IN_F / 4); i += 256) {
        const int r = i >> 5;        // row within tile
        const int c = i & 31;        // float4 index within row
        const int m = m0 + r;
        float4 v = make_float4(0.f, 0.f, 0.f, 0.f);
        if (m < N_NODES) {
            v = agg4[(size_t)m * (IN_F / 4) + c];
            const float s = invdeg[r];
            v.x *= s; v.y *= s; v.z *= s; v.w *= s;
        }
        reinterpret_cast<float4*>(Hsm)[i] = v;
    }
    __syncthreads();

    // Microtile: rowg = tid/16 (4 rows each), colg = tid%16 (8 cols each)
    const int rowg = tid >> 4;
    const int colg = tid & 15;
    const int r0   = rowg * 4;
    const int n0   = colg * 8;

    float acc[4][8];
    #pragma unroll
    for (int i = 0; i < 4; i++)
        #pragma unroll
        for (int j = 0; j < 8; j++) acc[i][j] = 0.0f;

    #pragma unroll 8
    for (int k = 0; k < IN_F; k++) {
        float4 w0 = *reinterpret_cast<const float4*>(&Wsm[k * OUT_F + n0]);
        float4 w1 = *reinterpret_cast<const float4*>(&Wsm[k * OUT_F + n0 + 4]);
        float a[4];
        #pragma unroll
        for (int i = 0; i < 4; i++) a[i] = Hsm[(r0 + i) * IN_F + k];
        #pragma unroll
        for (int i = 0; i < 4; i++) {
            acc[i][0] += a[i] * w0.x; acc[i][1] += a[i] * w0.y;
            acc[i][2] += a[i] * w0.z; acc[i][3] += a[i] * w0.w;
            acc[i][4] += a[i] * w1.x; acc[i][5] += a[i] * w1.y;
            acc[i][6] += a[i] * w1.z; acc[i][7] += a[i] * w1.w;
        }
    }

    // Bias + store
    float bb[8];
    #pragma unroll
    for (int j = 0; j < 8; j++) bb[j] = b[n0 + j];

    #pragma unroll
    for (int i = 0; i < 4; i++) {
        const int m = m0 + r0 + i;
        if (m < N_NODES) {
            float4 o0 = make_float4(acc[i][0] + bb[0], acc[i][1] + bb[1],
                                    acc[i][2] + bb[2], acc[i][3] + bb[3]);
            float4 o1 = make_float4(acc[i][4] + bb[4], acc[i][5] + bb[5],
                                    acc[i][6] + bb[6], acc[i][7] + bb[7]);
            float4* orow = reinterpret_cast<float4*>(out + (size_t)m * OUT_F + n0);
            orow[0] = o0;
            orow[1] = o1;
        }
    }
}

// ---------------------------------------------------------------------------
// kernel_launch
// ---------------------------------------------------------------------------
extern "C" void kernel_launch(void* const* d_in, const int* in_sizes, int n_in,
                              void* d_out, int out_size) {
    const float* x  = nullptr;
    const int*   ei = nullptr;
    const float* W  = nullptr;
    const float* b  = nullptr;

    for (int i = 0; i < n_in; i++) {
        switch (in_sizes[i]) {
            case N_NODES * IN_F:  x  = (const float*)d_in[i]; break; // 6.4M
            case 2 * N_EDGES:     ei = (const int*)d_in[i];   break; // 1.6M
            case OUT_F * IN_F:    W  = (const float*)d_in[i]; break; // 16384
            case OUT_F:           b  = (const float*)d_in[i]; break; // 128
            default: break; // n_nodes scalar etc.
        }
    }

    float* out = (float*)d_out;

    // 1) zero scratch
    zero_kernel<<<2048, 256>>>();

    // 2) scatter: 8 warps/block, 1 edge/warp
    const int edge_blocks = (N_EDGES + 7) / 8;  // 100000
    scatter_kernel<<<edge_blocks, 256>>>(reinterpret_cast<const float4*>(x), ei);

    // 3) fused normalize + GEMM + bias
    const int smem_bytes = (IN_F * OUT_F + TILE_M * IN_F + TILE_M) * (int)sizeof(float);
    cudaFuncSetAttribute(gemm_kernel, cudaFuncAttributeMaxDynamicSharedMemorySize,
                         smem_bytes);
    const int gemm_blocks = (N_NODES + TILE_M - 1) / TILE_M;  // 782
    gemm_kernel<<<gemm_blocks, 256, smem_bytes>>>(out, W, b);
}

// round 3
// speedup vs baseline: 1.1655x; 1.1655x over previous
#include <cuda_runtime.h>
#include <cuda_bf16.h>
#include <stdint.h>

#define N_NODES  50000
#define N_EDGES  800000
#define IN_F     128
#define OUT_F    128

#define SCAN_T   256
#define SCAN_B   ((N_NODES + SCAN_T - 1) / SCAN_T)   // 196

// -------------------- device scratch (no allocation allowed) ---------------
__device__ __align__(16) float g_agg[N_NODES * IN_F];  // normalized h rows
__device__ int   g_cnt[N_NODES];     // in-degree histogram
__device__ int   g_off[N_NODES];     // CSR row start
__device__ int   g_cur[N_NODES];     // fill cursor
__device__ int   g_srcs[N_EDGES];    // edge sources grouped by dst
__device__ int   g_bsums[SCAN_B];
__device__ int   g_bscan[SCAN_B];

// -------------------- 1) zero histogram -----------------------------------
__global__ void zero_cnt_kernel() {
    int gid = blockIdx.x * blockDim.x + threadIdx.x;
    if (gid < N_NODES) g_cnt[gid] = 0;
}

// -------------------- 2) histogram of destinations -------------------------
__global__ void hist_kernel(const int* __restrict__ ei) {
    int e = blockIdx.x * blockDim.x + threadIdx.x;
    if (e >= N_EDGES) return;
    int dst = ei[N_EDGES + e];
    dst = min(max(dst, 0), N_NODES - 1);
    atomicAdd(&g_cnt[dst], 1);
}

// -------------------- 3) exclusive scan (3 tiny kernels) -------------------
__global__ void scan1_kernel() {   // per-block sums
    __shared__ int s[SCAN_T];
    int gid = blockIdx.x * SCAN_T + threadIdx.x;
    s[threadIdx.x] = (gid < N_NODES) ? g_cnt[gid] : 0;
    __syncthreads();
    #pragma unroll
    for (int o = SCAN_T / 2; o > 0; o >>= 1) {
        if (threadIdx.x < o) s[threadIdx.x] += s[threadIdx.x + o];
        __syncthreads();
    }
    if (threadIdx.x == 0) g_bsums[blockIdx.x] = s[0];
}

__global__ void scan2_kernel() {   // exclusive scan of block sums (1 block)
    __shared__ int s[SCAN_T];
    int v = (threadIdx.x < SCAN_B) ? g_bsums[threadIdx.x] : 0;
    s[threadIdx.x] = v;
    __syncthreads();
    #pragma unroll
    for (int o = 1; o < SCAN_T; o <<= 1) {
        int t = (threadIdx.x >= o) ? s[threadIdx.x - o] : 0;
        __syncthreads();
        s[threadIdx.x] += t;
        __syncthreads();
    }
    if (threadIdx.x < SCAN_B) g_bscan[threadIdx.x] = s[threadIdx.x] - v;
}

__global__ void scan3_kernel() {   // per-element exclusive scan + block offset
    __shared__ int s[SCAN_T];
    int gid = blockIdx.x * SCAN_T + threadIdx.x;
    int v = (gid < N_NODES) ? g_cnt[gid] : 0;
    s[threadIdx.x] = v;
    __syncthreads();
    #pragma unroll
    for (int o = 1; o < SCAN_T; o <<= 1) {
        int t = (threadIdx.x >= o) ? s[threadIdx.x - o] : 0;
        __syncthreads();
        s[threadIdx.x] += t;
        __syncthreads();
    }
    int excl = s[threadIdx.x] - v + g_bscan[blockIdx.x];
    if (gid < N_NODES) { g_off[gid] = excl; g_cur[gid] = excl; }
}

// -------------------- 4) bucket-fill: group srcs by dst --------------------
__global__ void fill_kernel(const int* __restrict__ ei) {
    int e = blockIdx.x * blockDim.x + threadIdx.x;
    if (e >= N_EDGES) return;
    int src = ei[e];
    int dst = ei[N_EDGES + e];
    src = min(max(src, 0), N_NODES - 1);
    dst = min(max(dst, 0), N_NODES - 1);
    int pos = atomicAdd(&g_cur[dst], 1);
    g_srcs[pos] = src;
}

// -------------------- 5) gather-aggregate: one warp per node ---------------
// Reads x rows for all in-edges (L2-resident), accumulates in registers,
// writes the degree-normalized h row exactly once.
__global__ void __launch_bounds__(256)
agg_kernel(const float4* __restrict__ x4) {
    const int node = (blockIdx.x * blockDim.x + threadIdx.x) >> 5;
    if (node >= N_NODES) return;
    const int lane = threadIdx.x & 31;

    const int start = g_off[node];
    const int cnt   = g_cnt[node];
    const int end   = start + cnt;

    float4 a0 = make_float4(0.f, 0.f, 0.f, 0.f);
    float4 a1 = make_float4(0.f, 0.f, 0.f, 0.f);
    float4 a2 = make_float4(0.f, 0.f, 0.f, 0.f);
    float4 a3 = make_float4(0.f, 0.f, 0.f, 0.f);

    int e = start;
    // unroll-4: 4 independent loads in flight per iteration
    for (; e + 3 < end; e += 4) {
        const int s0 = g_srcs[e], s1 = g_srcs[e + 1];
        const int s2 = g_srcs[e + 2], s3 = g_srcs[e + 3];
        float4 v0 = __ldg(&x4[s0 * (IN_F / 4) + lane]);
        float4 v1 = __ldg(&x4[s1 * (IN_F / 4) + lane]);
        float4 v2 = __ldg(&x4[s2 * (IN_F / 4) + lane]);
        float4 v3 = __ldg(&x4[s3 * (IN_F / 4) + lane]);
        a0.x += v0.x; a0.y += v0.y; a0.z += v0.z; a0.w += v0.w;
        a1.x += v1.x; a1.y += v1.y; a1.z += v1.z; a1.w += v1.w;
        a2.x += v2.x; a2.y += v2.y; a2.z += v2.z; a2.w += v2.w;
        a3.x += v3.x; a3.y += v3.y; a3.z += v3.z; a3.w += v3.w;
    }
    for (; e < end; e++) {
        const int s0 = g_srcs[e];
        float4 v0 = __ldg(&x4[s0 * (IN_F / 4) + lane]);
        a0.x += v0.x; a0.y += v0.y; a0.z += v0.z; a0.w += v0.w;
    }

    const float inv = 1.0f / fmaxf((float)cnt, 1.0f);
    float4 r;
    r.x = (a0.x + a1.x + a2.x + a3.x) * inv;
    r.y = (a0.y + a1.y + a2.y + a3.y) * inv;
    r.z = (a0.z + a1.z + a2.z + a3.z) * inv;
    r.w = (a0.w + a1.w + a2.w + a3.w) * inv;
    reinterpret_cast<float4*>(g_agg)[(size_t)node * (IN_F / 4) + lane] = r;
}

// -------------------- 6) GEMM: out = h @ W^T + b ---------------------------
// h already normalized. Block tile 64x128, 256 threads, 4x8 microtile.
#define TILE_M 64
__global__ void __launch_bounds__(256, 1)
gemm_kernel(float* __restrict__ out, const float* __restrict__ W,
            const float* __restrict__ b) {
    extern __shared__ float sm[];
    float* Wsm = sm;                  // [k][n], 64KB
    float* Hsm = sm + IN_F * OUT_F;   // [TILE_M][128], 32KB

    const int tid = threadIdx.x;
    const int m0  = blockIdx.x * TILE_M;

    #pragma unroll 4
    for (int i = tid; i < OUT_F * IN_F; i += 256) {
        const int n = i >> 7;
        const int k = i & 127;
        Wsm[k * OUT_F + n] = W[i];
    }

    const float4* agg4 = reinterpret_cast<const float4*>(g_agg);
    #pragma unroll 2
    for (int i = tid; i < TILE_M * (IN_F / 4); i += 256) {
        const int r = i >> 5;
        const int c = i & 31;
        const int m = m0 + r;
        float4 v = make_float4(0.f, 0.f, 0.f, 0.f);
        if (m < N_NODES) v = agg4[(size_t)m * (IN_F / 4) + c];
        reinterpret_cast<float4*>(Hsm)[i] = v;
    }
    __syncthreads();

    const int rowg = tid >> 4;
    const int colg = tid & 15;
    const int r0   = rowg * 4;
    const int n0   = colg * 8;

    float acc[4][8];
    #pragma unroll
    for (int i = 0; i < 4; i++)
        #pragma unroll
        for (int j = 0; j < 8; j++) acc[i][j] = 0.0f;

    #pragma unroll 8
    for (int k = 0; k < IN_F; k++) {
        float4 w0 = *reinterpret_cast<const float4*>(&Wsm[k * OUT_F + n0]);
        float4 w1 = *reinterpret_cast<const float4*>(&Wsm[k * OUT_F + n0 + 4]);
        float a[4];
        #pragma unroll
        for (int i = 0; i < 4; i++) a[i] = Hsm[(r0 + i) * IN_F + k];
        #pragma unroll
        for (int i = 0; i < 4; i++) {
            acc[i][0] += a[i] * w0.x; acc[i][1] += a[i] * w0.y;
            acc[i][2] += a[i] * w0.z; acc[i][3] += a[i] * w0.w;
            acc[i][4] += a[i] * w1.x; acc[i][5] += a[i] * w1.y;
            acc[i][6] += a[i] * w1.z; acc[i][7] += a[i] * w1.w;
        }
    }

    float bb[8];
    #pragma unroll
    for (int j = 0; j < 8; j++) bb[j] = b[n0 + j];

    #pragma unroll
    for (int i = 0; i < 4; i++) {
        const int m = m0 + r0 + i;
        if (m < N_NODES) {
            float4 o0 = make_float4(acc[i][0] + bb[0], acc[i][1] + bb[1],
                                    acc[i][2] + bb[2], acc[i][3] + bb[3]);
            float4 o1 = make_float4(acc[i][4] + bb[4], acc[i][5] + bb[5],
                                    acc[i][6] + bb[6], acc[i][7] + bb[7]);
            float4* orow = reinterpret_cast<float4*>(out + (size_t)m * OUT_F + n0);
            orow[0] = o0;
            orow[1] = o1;
        }
    }
}

// ---------------------------------------------------------------------------
extern "C" void kernel_launch(void* const* d_in, const int* in_sizes, int n_in,
                              void* d_out, int out_size) {
    const float* x  = nullptr;
    const int*   ei = nullptr;
    const float* W  = nullptr;
    const float* b  = nullptr;

    for (int i = 0; i < n_in; i++) {
        switch (in_sizes[i]) {
            case N_NODES * IN_F:  x  = (const float*)d_in[i]; break;
            case 2 * N_EDGES:     ei = (const int*)d_in[i];   break;
            case OUT_F * IN_F:    W  = (const float*)d_in[i]; break;
            case OUT_F:           b  = (const float*)d_in[i]; break;
            default: break;
        }
    }

    float* out = (float*)d_out;

    zero_cnt_kernel<<<SCAN_B, SCAN_T>>>();
    hist_kernel<<<(N_EDGES + 255) / 256, 256>>>(ei);
    scan1_kernel<<<SCAN_B, SCAN_T>>>();
    scan2_kernel<<<1, SCAN_T>>>();
    scan3_kernel<<<SCAN_B, SCAN_T>>>();
    fill_kernel<<<(N_EDGES + 255) / 256, 256>>>(ei);

    const int agg_blocks = (N_NODES * 32 + 255) / 256;   // 6250
    agg_kernel<<<agg_blocks, 256>>>(reinterpret_cast<const float4*>(x));

    const int smem_bytes = (IN_F * OUT_F + TILE_M * IN_F) * (int)sizeof(float);
    cudaFuncSetAttribute(gemm_kernel, cudaFuncAttributeMaxDynamicSharedMemorySize,
                         smem_bytes);
    gemm_kernel<<<(N_NODES + TILE_M - 1) / TILE_M, 256, smem_bytes>>>(out, W, b);
}

// round 4
// speedup vs baseline: 1.6317x; 1.4000x over previous
#include <cuda_runtime.h>
#include <cuda_bf16.h>
#include <stdint.h>

#define N_NODES  50000
#define N_EDGES  800000
#define IN_F     128
#define OUT_F    128

#define SCAN_T   256
#define SCAN_B   ((N_NODES + SCAN_T - 1) / SCAN_T)   // 196

// -------------------- device scratch (no allocation allowed) ---------------
__device__ __align__(16) float g_agg[N_NODES * IN_F];  // normalized h rows
__device__ int   g_cnt[N_NODES];     // in-degree histogram
__device__ int   g_off[N_NODES];     // CSR row start
__device__ int   g_cur[N_NODES];     // fill cursor
__device__ int   g_srcs[N_EDGES];    // edge sources grouped by dst
__device__ int   g_bsums[SCAN_B];

// -------------------- 1) histogram of destinations -------------------------
__global__ void hist_kernel(const int* __restrict__ ei) {
    int e = blockIdx.x * blockDim.x + threadIdx.x;
    if (e >= N_EDGES) return;
    int dst = ei[N_EDGES + e];
    dst = min(max(dst, 0), N_NODES - 1);
    atomicAdd(&g_cnt[dst], 1);
}

// -------------------- 2) scanA: per-block sums -----------------------------
__global__ void scanA_kernel() {
    __shared__ int s[SCAN_T];
    int gid = blockIdx.x * SCAN_T + threadIdx.x;
    s[threadIdx.x] = (gid < N_NODES) ? g_cnt[gid] : 0;
    __syncthreads();
    #pragma unroll
    for (int o = SCAN_T / 2; o > 0; o >>= 1) {
        if (threadIdx.x < o) s[threadIdx.x] += s[threadIdx.x + o];
        __syncthreads();
    }
    if (threadIdx.x == 0) g_bsums[blockIdx.x] = s[0];
}

// -------------------- 3) scanB: full exclusive scan ------------------------
// Each block redundantly scans the 196 block sums (cheap, removes a launch),
// then scans its own tile and writes off/cur.
__global__ void scanB_kernel() {
    __shared__ int sb[SCAN_T];
    __shared__ int st[SCAN_T];
    const int tid = threadIdx.x;

    int bv = (tid < SCAN_B) ? g_bsums[tid] : 0;
    sb[tid] = bv;
    __syncthreads();
    #pragma unroll
    for (int o = 1; o < SCAN_T; o <<= 1) {
        int t = (tid >= o) ? sb[tid - o] : 0;
        __syncthreads();
        sb[tid] += t;
        __syncthreads();
    }
    const int base = (blockIdx.x > 0) ? sb[blockIdx.x - 1] : 0;

    const int gid = blockIdx.x * SCAN_T + tid;
    int c = (gid < N_NODES) ? g_cnt[gid] : 0;
    st[tid] = c;
    __syncthreads();
    #pragma unroll
    for (int o = 1; o < SCAN_T; o <<= 1) {
        int t = (tid >= o) ? st[tid - o] : 0;
        __syncthreads();
        st[tid] += t;
        __syncthreads();
    }
    if (gid < N_NODES) {
        const int excl = base + st[tid] - c;
        g_off[gid] = excl;
        g_cur[gid] = excl;
    }
}

// -------------------- 4) bucket-fill: group srcs by dst --------------------
__global__ void fill_kernel(const int* __restrict__ ei) {
    int e = blockIdx.x * blockDim.x + threadIdx.x;
    if (e >= N_EDGES) return;
    int src = ei[e];
    int dst = ei[N_EDGES + e];
    src = min(max(src, 0), N_NODES - 1);
    dst = min(max(dst, 0), N_NODES - 1);
    int pos = atomicAdd(&g_cur[dst], 1);
    g_srcs[pos] = src;
}

// -------------------- 5) gather-aggregate: one warp per node ---------------
// Unroll-8 main loop for deep MLP; x rows are L2-resident.
__global__ void __launch_bounds__(256)
agg_kernel(const float4* __restrict__ x4) {
    const int node = (blockIdx.x * blockDim.x + threadIdx.x) >> 5;
    if (node >= N_NODES) return;
    const int lane = threadIdx.x & 31;

    const int start = g_off[node];
    const int cnt   = g_cnt[node];
    const int end   = start + cnt;

    float4 a0 = make_float4(0.f, 0.f, 0.f, 0.f);
    float4 a1 = make_float4(0.f, 0.f, 0.f, 0.f);
    float4 a2 = make_float4(0.f, 0.f, 0.f, 0.f);
    float4 a3 = make_float4(0.f, 0.f, 0.f, 0.f);

    int e = start;
    for (; e + 7 < end; e += 8) {
        int s0 = g_srcs[e],     s1 = g_srcs[e + 1];
        int s2 = g_srcs[e + 2], s3 = g_srcs[e + 3];
        int s4 = g_srcs[e + 4], s5 = g_srcs[e + 5];
        int s6 = g_srcs[e + 6], s7 = g_srcs[e + 7];
        float4 v0 = __ldg(&x4[s0 * 32 + lane]);
        float4 v1 = __ldg(&x4[s1 * 32 + lane]);
        float4 v2 = __ldg(&x4[s2 * 32 + lane]);
        float4 v3 = __ldg(&x4[s3 * 32 + lane]);
        float4 v4 = __ldg(&x4[s4 * 32 + lane]);
        float4 v5 = __ldg(&x4[s5 * 32 + lane]);
        float4 v6 = __ldg(&x4[s6 * 32 + lane]);
        float4 v7 = __ldg(&x4[s7 * 32 + lane]);
        a0.x += v0.x; a0.y += v0.y; a0.z += v0.z; a0.w += v0.w;
        a1.x += v1.x; a1.y += v1.y; a1.z += v1.z; a1.w += v1.w;
        a2.x += v2.x; a2.y += v2.y; a2.z += v2.z; a2.w += v2.w;
        a3.x += v3.x; a3.y += v3.y; a3.z += v3.z; a3.w += v3.w;
        a0.x += v4.x; a0.y += v4.y; a0.z += v4.z; a0.w += v4.w;
        a1.x += v5.x; a1.y += v5.y; a1.z += v5.z; a1.w += v5.w;
        a2.x += v6.x; a2.y += v6.y; a2.z += v6.z; a2.w += v6.w;
        a3.x += v7.x; a3.y += v7.y; a3.z += v7.z; a3.w += v7.w;
    }
    for (; e + 3 < end; e += 4) {
        int s0 = g_srcs[e],     s1 = g_srcs[e + 1];
        int s2 = g_srcs[e + 2], s3 = g_srcs[e + 3];
        float4 v0 = __ldg(&x4[s0 * 32 + lane]);
        float4 v1 = __ldg(&x4[s1 * 32 + lane]);
        float4 v2 = __ldg(&x4[s2 * 32 + lane]);
        float4 v3 = __ldg(&x4[s3 * 32 + lane]);
        a0.x += v0.x; a0.y += v0.y; a0.z += v0.z; a0.w += v0.w;
        a1.x += v1.x; a1.y += v1.y; a1.z += v1.z; a1.w += v1.w;
        a2.x += v2.x; a2.y += v2.y; a2.z += v2.z; a2.w += v2.w;
        a3.x += v3.x; a3.y += v3.y; a3.z += v3.z; a3.w += v3.w;
    }
    for (; e < end; e++) {
        int s0 = g_srcs[e];
        float4 v0 = __ldg(&x4[s0 * 32 + lane]);
        a0.x += v0.x; a0.y += v0.y; a0.z += v0.z; a0.w += v0.w;
    }

    const float inv = 1.0f / fmaxf((float)cnt, 1.0f);
    float4 r;
    r.x = (a0.x + a1.x + a2.x + a3.x) * inv;
    r.y = (a0.y + a1.y + a2.y + a3.y) * inv;
    r.z = (a0.z + a1.z + a2.z + a3.z) * inv;
    r.w = (a0.w + a1.w + a2.w + a3.w) * inv;
    reinterpret_cast<float4*>(g_agg)[(size_t)node * 32 + lane] = r;
}

// -------------------- 6) GEMM: out = h @ W^T + b ---------------------------
// TILE_M=128, 256 threads, 8x8 microtile, packed fma.rn.f32x2 (2 FLOP/lane/instr).
#define TILE_M 128
__global__ void __launch_bounds__(256, 1)
gemm_kernel(float* __restrict__ out, const float* __restrict__ W,
            const float* __restrict__ b) {
    extern __shared__ float sm[];
    float* Wsm = sm;                  // [k][n] 128x128 = 64KB
    float* Hsm = sm + IN_F * OUT_F;   // [m][k] 128x128 = 64KB

    const int tid = threadIdx.x;
    const int m0  = blockIdx.x * TILE_M;

    // Stage W transposed: Wsm[k*128 + n] = W[n*128 + k]
    #pragma unroll 4
    for (int i = tid; i < OUT_F * IN_F; i += 256) {
        const int n = i >> 7;
        const int k = i & 127;
        Wsm[k * OUT_F + n] = W[i];
    }

    // Stage H tile (zero-pad past N_NODES)
    const float4* agg4 = reinterpret_cast<const float4*>(g_agg);
    float4* Hsm4 = reinterpret_cast<float4*>(Hsm);
    #pragma unroll 4
    for (int i = tid; i < TILE_M * 32; i += 256) {
        const int r = i >> 5;
        const int c = i & 31;
        const int m = m0 + r;
        float4 v = make_float4(0.f, 0.f, 0.f, 0.f);
        if (m < N_NODES) v = agg4[(size_t)m * 32 + c];
        Hsm4[i] = v;
    }
    __syncthreads();

    const int rowg = tid >> 4;      // 16 groups of 8 rows
    const int colg = tid & 15;      // 16 groups of 8 cols
    const int r0   = rowg * 8;
    const int n0   = colg * 8;

    unsigned long long acc[8][4];   // 8 rows x 4 f32x2 pairs (8 cols)
    #pragma unroll
    for (int i = 0; i < 8; i++)
        #pragma unroll
        for (int j = 0; j < 4; j++) acc[i][j] = 0ULL;

    for (int kk = 0; kk < IN_F; kk += 4) {
        float4 h4[8];
        #pragma unroll
        for (int i = 0; i < 8; i++)
            h4[i] = Hsm4[(r0 + i) * 32 + (kk >> 2)];

        #pragma unroll
        for (int j = 0; j < 4; j++) {
            const ulonglong2 wA = *reinterpret_cast<const ulonglong2*>(
                &Wsm[(kk + j) * OUT_F + n0]);
            const ulonglong2 wB = *reinterpret_cast<const ulonglong2*>(
                &Wsm[(kk + j) * OUT_F + n0 + 4]);
            #pragma unroll
            for (int i = 0; i < 8; i++) {
                const float a = (j == 0) ? h4[i].x : (j == 1) ? h4[i].y
                              : (j == 2) ? h4[i].z : h4[i].w;
                unsigned long long aa;
                asm("mov.b64 %0, {%1, %1};" : "=l"(aa) : "f"(a));
                asm("fma.rn.f32x2 %0, %1, %2, %0;" : "+l"(acc[i][0]) : "l"(aa), "l"(wA.x));
                asm("fma.rn.f32x2 %0, %1, %2, %0;" : "+l"(acc[i][1]) : "l"(aa), "l"(wA.y));
                asm("fma.rn.f32x2 %0, %1, %2, %0;" : "+l"(acc[i][2]) : "l"(aa), "l"(wB.x));
                asm("fma.rn.f32x2 %0, %1, %2, %0;" : "+l"(acc[i][3]) : "l"(aa), "l"(wB.y));
            }
        }
    }

    // Bias + store
    float bb[8];
    #pragma unroll
    for (int j = 0; j < 8; j++) bb[j] = b[n0 + j];

    #pragma unroll
    for (int i = 0; i < 8; i++) {
        const int m = m0 + r0 + i;
        if (m < N_NODES) {
            float lo, hi;
            float o[8];
            #pragma unroll
            for (int j = 0; j < 4; j++) {
                asm("mov.b64 {%0, %1}, %2;" : "=f"(lo), "=f"(hi) : "l"(acc[i][j]));
                o[2 * j]     = lo + bb[2 * j];
                o[2 * j + 1] = hi + bb[2 * j + 1];
            }
            float4* orow = reinterpret_cast<float4*>(out + (size_t)m * OUT_F + n0);
            orow[0] = make_float4(o[0], o[1], o[2], o[3]);
            orow[1] = make_float4(o[4], o[5], o[6], o[7]);
        }
    }
}

// ---------------------------------------------------------------------------
extern "C" void kernel_launch(void* const* d_in, const int* in_sizes, int n_in,
                              void* d_out, int out_size) {
    const float* x  = nullptr;
    const int*   ei = nullptr;
    const float* W  = nullptr;
    const float* b  = nullptr;

    for (int i = 0; i < n_in; i++) {
        switch (in_sizes[i]) {
            case N_NODES * IN_F:  x  = (const float*)d_in[i]; break;
            case 2 * N_EDGES:     ei = (const int*)d_in[i];   break;
            case OUT_F * IN_F:    W  = (const float*)d_in[i]; break;
            case OUT_F:           b  = (const float*)d_in[i]; break;
            default: break;
        }
    }

    float* out = (float*)d_out;

    // zero histogram via memset (no kernel launch)
    void* cnt_ptr = nullptr;
    cudaGetSymbolAddress(&cnt_ptr, g_cnt);
    cudaMemsetAsync(cnt_ptr, 0, N_NODES * sizeof(int));

    hist_kernel<<<(N_EDGES + 255) / 256, 256>>>(ei);
    scanA_kernel<<<SCAN_B, SCAN_T>>>();
    scanB_kernel<<<SCAN_B, SCAN_T>>>();
    fill_kernel<<<(N_EDGES + 255) / 256, 256>>>(ei);

    const int agg_blocks = (N_NODES * 32 + 255) / 256;   // 6250
    agg_kernel<<<agg_blocks, 256>>>(reinterpret_cast<const float4*>(x));

    const int smem_bytes = 2 * IN_F * OUT_F * (int)sizeof(float);  // 128KB
    cudaFuncSetAttribute(gemm_kernel, cudaFuncAttributeMaxDynamicSharedMemorySize,
                         smem_bytes);
    gemm_kernel<<<(N_NODES + TILE_M - 1) / TILE_M, 256, smem_bytes>>>(out, W, b);
}

// round 5
// speedup vs baseline: 1.8940x; 1.1607x over previous
#include <cuda_runtime.h>
#include <cuda_bf16.h>
#include <stdint.h>

#define N_NODES  50000
#define N_EDGES  800000
#define IN_F     128
#define OUT_F    128

#define SCAN_T   256
#define SCAN_B   ((N_NODES + SCAN_T - 1) / SCAN_T)   // 196

#define NUM_SM   148
#define TILE_M   128
#define N_TILES  ((N_NODES + TILE_M - 1) / TILE_M)   // 391

// -------------------- device scratch (no allocation allowed) ---------------
__device__ __align__(16) float g_agg[N_NODES * IN_F];  // normalized h rows
__device__ int   g_cnt[N_NODES];     // in-degree histogram
__device__ int   g_off[N_NODES];     // CSR row start
__device__ int   g_cur[N_NODES];     // fill cursor
__device__ int   g_srcs[N_EDGES];    // edge sources grouped by dst
__device__ int   g_bsums[SCAN_B];

// -------------------- 1) histogram of destinations (4 edges/thread) --------
__global__ void hist_kernel(const int* __restrict__ ei) {
    const int e4 = blockIdx.x * blockDim.x + threadIdx.x;
    if (e4 >= N_EDGES / 4) return;
    int4 d = reinterpret_cast<const int4*>(ei + N_EDGES)[e4];
    d.x = min(max(d.x, 0), N_NODES - 1);
    d.y = min(max(d.y, 0), N_NODES - 1);
    d.z = min(max(d.z, 0), N_NODES - 1);
    d.w = min(max(d.w, 0), N_NODES - 1);
    atomicAdd(&g_cnt[d.x], 1);
    atomicAdd(&g_cnt[d.y], 1);
    atomicAdd(&g_cnt[d.z], 1);
    atomicAdd(&g_cnt[d.w], 1);
}

// -------------------- 2) scanA: per-block sums -----------------------------
__global__ void scanA_kernel() {
    __shared__ int s[SCAN_T];
    int gid = blockIdx.x * SCAN_T + threadIdx.x;
    s[threadIdx.x] = (gid < N_NODES) ? g_cnt[gid] : 0;
    __syncthreads();
    #pragma unroll
    for (int o = SCAN_T / 2; o > 0; o >>= 1) {
        if (threadIdx.x < o) s[threadIdx.x] += s[threadIdx.x + o];
        __syncthreads();
    }
    if (threadIdx.x == 0) g_bsums[blockIdx.x] = s[0];
}

// -------------------- 3) scanB: full exclusive scan ------------------------
__global__ void scanB_kernel() {
    __shared__ int sb[SCAN_T];
    __shared__ int st[SCAN_T];
    const int tid = threadIdx.x;

    int bv = (tid < SCAN_B) ? g_bsums[tid] : 0;
    sb[tid] = bv;
    __syncthreads();
    #pragma unroll
    for (int o = 1; o < SCAN_T; o <<= 1) {
        int t = (tid >= o) ? sb[tid - o] : 0;
        __syncthreads();
        sb[tid] += t;
        __syncthreads();
    }
    const int base = (blockIdx.x > 0) ? sb[blockIdx.x - 1] : 0;

    const int gid = blockIdx.x * SCAN_T + tid;
    int c = (gid < N_NODES) ? g_cnt[gid] : 0;
    st[tid] = c;
    __syncthreads();
    #pragma unroll
    for (int o = 1; o < SCAN_T; o <<= 1) {
        int t = (tid >= o) ? st[tid - o] : 0;
        __syncthreads();
        st[tid] += t;
        __syncthreads();
    }
    if (gid < N_NODES) {
        const int excl = base + st[tid] - c;
        g_off[gid] = excl;
        g_cur[gid] = excl;
    }
}

// -------------------- 4) bucket-fill (4 edges/thread, 4 chains in flight) --
__global__ void fill_kernel(const int* __restrict__ ei) {
    const int e4 = blockIdx.x * blockDim.x + threadIdx.x;
    if (e4 >= N_EDGES / 4) return;
    int4 s = reinterpret_cast<const int4*>(ei)[e4];
    int4 d = reinterpret_cast<const int4*>(ei + N_EDGES)[e4];
    s.x = min(max(s.x, 0), N_NODES - 1);
    s.y = min(max(s.y, 0), N_NODES - 1);
    s.z = min(max(s.z, 0), N_NODES - 1);
    s.w = min(max(s.w, 0), N_NODES - 1);
    d.x = min(max(d.x, 0), N_NODES - 1);
    d.y = min(max(d.y, 0), N_NODES - 1);
    d.z = min(max(d.z, 0), N_NODES - 1);
    d.w = min(max(d.w, 0), N_NODES - 1);
    // 4 independent atomic round-trips issue back-to-back
    int p0 = atomicAdd(&g_cur[d.x], 1);
    int p1 = atomicAdd(&g_cur[d.y], 1);
    int p2 = atomicAdd(&g_cur[d.z], 1);
    int p3 = atomicAdd(&g_cur[d.w], 1);
    g_srcs[p0] = s.x;
    g_srcs[p1] = s.y;
    g_srcs[p2] = s.z;
    g_srcs[p3] = s.w;
}

// -------------------- 5) gather-aggregate: one warp per node ---------------
__global__ void __launch_bounds__(256)
agg_kernel(const float4* __restrict__ x4) {
    const int node = (blockIdx.x * blockDim.x + threadIdx.x) >> 5;
    if (node >= N_NODES) return;
    const int lane = threadIdx.x & 31;

    const int start = g_off[node];
    const int cnt   = g_cnt[node];
    const int end   = start + cnt;

    float4 a0 = make_float4(0.f, 0.f, 0.f, 0.f);
    float4 a1 = make_float4(0.f, 0.f, 0.f, 0.f);
    float4 a2 = make_float4(0.f, 0.f, 0.f, 0.f);
    float4 a3 = make_float4(0.f, 0.f, 0.f, 0.f);

    int e = start;
    for (; e + 7 < end; e += 8) {
        int s0 = g_srcs[e],     s1 = g_srcs[e + 1];
        int s2 = g_srcs[e + 2], s3 = g_srcs[e + 3];
        int s4 = g_srcs[e + 4], s5 = g_srcs[e + 5];
        int s6 = g_srcs[e + 6], s7 = g_srcs[e + 7];
        float4 v0 = __ldg(&x4[s0 * 32 + lane]);
        float4 v1 = __ldg(&x4[s1 * 32 + lane]);
        float4 v2 = __ldg(&x4[s2 * 32 + lane]);
        float4 v3 = __ldg(&x4[s3 * 32 + lane]);
        float4 v4 = __ldg(&x4[s4 * 32 + lane]);
        float4 v5 = __ldg(&x4[s5 * 32 + lane]);
        float4 v6 = __ldg(&x4[s6 * 32 + lane]);
        float4 v7 = __ldg(&x4[s7 * 32 + lane]);
        a0.x += v0.x; a0.y += v0.y; a0.z += v0.z; a0.w += v0.w;
        a1.x += v1.x; a1.y += v1.y; a1.z += v1.z; a1.w += v1.w;
        a2.x += v2.x; a2.y += v2.y; a2.z += v2.z; a2.w += v2.w;
        a3.x += v3.x; a3.y += v3.y; a3.z += v3.z; a3.w += v3.w;
        a0.x += v4.x; a0.y += v4.y; a0.z += v4.z; a0.w += v4.w;
        a1.x += v5.x; a1.y += v5.y; a1.z += v5.z; a1.w += v5.w;
        a2.x += v6.x; a2.y += v6.y; a2.z += v6.z; a2.w += v6.w;
        a3.x += v7.x; a3.y += v7.y; a3.z += v7.z; a3.w += v7.w;
    }
    for (; e + 3 < end; e += 4) {
        int s0 = g_srcs[e],     s1 = g_srcs[e + 1];
        int s2 = g_srcs[e + 2], s3 = g_srcs[e + 3];
        float4 v0 = __ldg(&x4[s0 * 32 + lane]);
        float4 v1 = __ldg(&x4[s1 * 32 + lane]);
        float4 v2 = __ldg(&x4[s2 * 32 + lane]);
        float4 v3 = __ldg(&x4[s3 * 32 + lane]);
        a0.x += v0.x; a0.y += v0.y; a0.z += v0.z; a0.w += v0.w;
        a1.x += v1.x; a1.y += v1.y; a1.z += v1.z; a1.w += v1.w;
        a2.x += v2.x; a2.y += v2.y; a2.z += v2.z; a2.w += v2.w;
        a3.x += v3.x; a3.y += v3.y; a3.z += v3.z; a3.w += v3.w;
    }
    for (; e < end; e++) {
        int s0 = g_srcs[e];
        float4 v0 = __ldg(&x4[s0 * 32 + lane]);
        a0.x += v0.x; a0.y += v0.y; a0.z += v0.z; a0.w += v0.w;
    }

    const float inv = 1.0f / fmaxf((float)cnt, 1.0f);
    float4 r;
    r.x = (a0.x + a1.x + a2.x + a3.x) * inv;
    r.y = (a0.y + a1.y + a2.y + a3.y) * inv;
    r.z = (a0.z + a1.z + a2.z + a3.z) * inv;
    r.w = (a0.w + a1.w + a2.w + a3.w) * inv;
    reinterpret_cast<float4*>(g_agg)[(size_t)node * 32 + lane] = r;
}

// -------------------- 6) persistent double-buffered GEMM -------------------
// out = h @ W^T + b.  148 resident blocks loop over 391 m-tiles.
// W staged once; next H tile prefetched via cp.async while computing current.
// smem = Wsm 64KB + 2 x Hbuf 64KB = 192KB.
__device__ __forceinline__ void issue_h_tile(int tile, float* buf, int tid) {
    const int m0 = tile * TILE_M;
    const float4* aggbase = reinterpret_cast<const float4*>(g_agg);
    #pragma unroll
    for (int j = 0; j < 16; j++) {
        const int i = tid + j * 256;        // element (float4) index in tile
        const int r = i >> 5;
        const int c = i & 31;
        const int m = min(m0 + r, N_NODES - 1);   // clamp: extra rows discarded at store
        const float4* src = aggbase + (size_t)m * 32 + c;
        unsigned saddr = (unsigned)__cvta_generic_to_shared(buf + i * 4);
        asm volatile("cp.async.cg.shared.global [%0], [%1], 16;"
                     :: "r"(saddr), "l"(src));
    }
    asm volatile("cp.async.commit_group;");
}

__global__ void __launch_bounds__(256, 1)
gemm_kernel(float* __restrict__ out, const float* __restrict__ W,
            const float* __restrict__ b) {
    extern __shared__ float sm[];
    float* Wsm   = sm;                       // [k][n] 64KB
    float* Hbuf0 = sm + IN_F * OUT_F;        // 64KB
    float* Hbuf1 = Hbuf0 + TILE_M * IN_F;    // 64KB

    const int tid = threadIdx.x;

    // Prefetch first tile immediately (overlaps with W staging)
    int tile0 = blockIdx.x;
    if (tile0 < N_TILES) issue_h_tile(tile0, Hbuf0, tid);

    // Stage W transposed: Wsm[k*128 + n] = W[n*128 + k]
    #pragma unroll 4
    for (int i = tid; i < OUT_F * IN_F; i += 256) {
        const int n = i >> 7;
        const int k = i & 127;
        Wsm[k * OUT_F + n] = W[i];
    }

    const int rowg = tid >> 4;
    const int colg = tid & 15;
    const int r0   = rowg * 8;
    const int n0   = colg * 8;

    float bb[8];
    #pragma unroll
    for (int j = 0; j < 8; j++) bb[j] = b[n0 + j];

    int it = 0;
    for (int tile = blockIdx.x; tile < N_TILES; tile += NUM_SM, it++) {
        float* cur = (it & 1) ? Hbuf1 : Hbuf0;
        float* nxt = (it & 1) ? Hbuf0 : Hbuf1;
        const int ntile = tile + NUM_SM;
        if (ntile < N_TILES) {
            issue_h_tile(ntile, nxt, tid);
            asm volatile("cp.async.wait_group 1;");
        } else {
            asm volatile("cp.async.wait_group 0;");
        }
        __syncthreads();   // cur tile visible to all warps (also covers W on it==0)

        const float4* Hsm4 = reinterpret_cast<const float4*>(cur);

        unsigned long long acc[8][4];
        #pragma unroll
        for (int i = 0; i < 8; i++)
            #pragma unroll
            for (int j = 0; j < 4; j++) acc[i][j] = 0ULL;

        for (int kk = 0; kk < IN_F; kk += 4) {
            float4 h4[8];
            #pragma unroll
            for (int i = 0; i < 8; i++)
                h4[i] = Hsm4[(r0 + i) * 32 + (kk >> 2)];

            #pragma unroll
            for (int j = 0; j < 4; j++) {
                const ulonglong2 wA = *reinterpret_cast<const ulonglong2*>(
                    &Wsm[(kk + j) * OUT_F + n0]);
                const ulonglong2 wB = *reinterpret_cast<const ulonglong2*>(
                    &Wsm[(kk + j) * OUT_F + n0 + 4]);
                #pragma unroll
                for (int i = 0; i < 8; i++) {
                    const float a = (j == 0) ? h4[i].x : (j == 1) ? h4[i].y
                                  : (j == 2) ? h4[i].z : h4[i].w;
                    unsigned long long aa;
                    asm("mov.b64 %0, {%1, %1};" : "=l"(aa) : "f"(a));
                    asm("fma.rn.f32x2 %0, %1, %2, %0;" : "+l"(acc[i][0]) : "l"(aa), "l"(wA.x));
                    asm("fma.rn.f32x2 %0, %1, %2, %0;" : "+l"(acc[i][1]) : "l"(aa), "l"(wA.y));
                    asm("fma.rn.f32x2 %0, %1, %2, %0;" : "+l"(acc[i][2]) : "l"(aa), "l"(wB.x));
                    asm("fma.rn.f32x2 %0, %1, %2, %0;" : "+l"(acc[i][3]) : "l"(aa), "l"(wB.y));
                }
            }
        }

        const int m0 = tile * TILE_M;
        #pragma unroll
        for (int i = 0; i < 8; i++) {
            const int m = m0 + r0 + i;
            if (m < N_NODES) {
                float lo, hi;
                float o[8];
                #pragma unroll
                for (int j = 0; j < 4; j++) {
                    asm("mov.b64 {%0, %1}, %2;" : "=f"(lo), "=f"(hi) : "l"(acc[i][j]));
                    o[2 * j]     = lo + bb[2 * j];
                    o[2 * j + 1] = hi + bb[2 * j + 1];
                }
                float4* orow = reinterpret_cast<float4*>(out + (size_t)m * OUT_F + n0);
                orow[0] = make_float4(o[0], o[1], o[2], o[3]);
                orow[1] = make_float4(o[4], o[5], o[6], o[7]);
            }
        }
        __syncthreads();   // all warps done with cur before it is refilled
    }
}

// ---------------------------------------------------------------------------
extern "C" void kernel_launch(void* const* d_in, const int* in_sizes, int n_in,
                              void* d_out, int out_size) {
    const float* x  = nullptr;
    const int*   ei = nullptr;
    const float* W  = nullptr;
    const float* b  = nullptr;

    for (int i = 0; i < n_in; i++) {
        switch (in_sizes[i]) {
            case N_NODES * IN_F:  x  = (const float*)d_in[i]; break;
            case 2 * N_EDGES:     ei = (const int*)d_in[i];   break;
            case OUT_F * IN_F:    W  = (const float*)d_in[i]; break;
            case OUT_F:           b  = (const float*)d_in[i]; break;
            default: break;
        }
    }

    float* out = (float*)d_out;

    void* cnt_ptr = nullptr;
    cudaGetSymbolAddress(&cnt_ptr, g_cnt);
    cudaMemsetAsync(cnt_ptr, 0, N_NODES * sizeof(int));

    hist_kernel<<<(N_EDGES / 4 + 255) / 256, 256>>>(ei);
    scanA_kernel<<<SCAN_B, SCAN_T>>>();
    scanB_kernel<<<SCAN_B, SCAN_T>>>();
    fill_kernel<<<(N_EDGES / 4 + 255) / 256, 256>>>(ei);

    const int agg_blocks = (N_NODES * 32 + 255) / 256;   // 6250
    agg_kernel<<<agg_blocks, 256>>>(reinterpret_cast<const float4*>(x));

    const int smem_bytes = 3 * IN_F * OUT_F * (int)sizeof(float);  // 192KB
    cudaFuncSetAttribute(gemm_kernel, cudaFuncAttributeMaxDynamicSharedMemorySize,
                         smem_bytes);
    gemm_kernel<<<NUM_SM, 256, smem_bytes>>>(out, W, b);
}